// round 14
// baseline (speedup 1.0000x reference)
#include <cuda_runtime.h>
#include <cuda_fp16.h>
#include <math.h>
#include <stdint.h>

// Problem constants
#define BB   4
#define LSEQ 4096
#define HD   1024
#define UD   1024
#define U3   3072
#define NCHUNK 64
#define LC     64
#define KH   1024           // operand K width (fp16)
#define MROWS (BB*LSEQ)     // 16384

// Scratch (allocation-free: __device__ globals)
__device__ __half g_rkv16[(size_t)BB * LSEQ * U3];     // 96 MB: sigmoid(r), exp(k), v
__device__ float g_part[(size_t)BB * NCHUNK * 2 * UD]; // 2 MB
__device__ __half g_A16[(size_t)MROWS * KH];           // 32 MB fp16(inputs)
__device__ __half g_X16[(size_t)MROWS * KH];           // 32 MB fp16(x), written by scan
__device__ __half g_B1[(size_t)U3 * KH];               //  6 MB T(W_rkv) fp16
__device__ __half g_B2[(size_t)HD * KH];               //  2 MB T(W_o) fp16

__device__ __forceinline__ void cpa16(void* s, const void* g) {
    uint32_t sa = (uint32_t)__cvta_generic_to_shared(s);
    asm volatile("cp.async.cg.shared.global [%0], [%1], 16;" :: "r"(sa), "l"(g));
}

#define HMMA(d, a, b) \
    asm volatile( \
        "mma.sync.aligned.m16n8k16.row.col.f32.f16.f16.f32 " \
        "{%0,%1,%2,%3},{%4,%5,%6,%7},{%8,%9},{%0,%1,%2,%3};" \
        : "+f"(d[0]), "+f"(d[1]), "+f"(d[2]), "+f"(d[3]) \
        : "r"(a[0]), "r"(a[1]), "r"(a[2]), "r"(a[3]), "r"(b[0]), "r"(b[1]))

// ---------------------------------------------------------------------------
// fp16 warp-MMA GEMM (mma.sync m16n8k16, fp32 accum), single product.
// 16 k64-chunks. CTA tile 128x128, 4 warps (2x2), warp tile 64x64, 128 thr,
// 2 CTAs/SM. 2-stage cp.async pipeline, ldmatrix.x4.
// SMEM rows: 128B data + 16B pad = 144B (conflict-free).
// Epilogue modes: fuse=1 -> per-segment nonlinearity (sigmoid/exp/id), fp16 out
//                 fuse=0 -> bias + fp32 out
// ---------------------------------------------------------------------------
#define RS    72                // row stride (fp16 elems) = 144 B
#define TEL   (128 * RS)
#define SEL   (2 * TEL)
#define STB   (SEL * 2)         // 36864 bytes
#define SMEM_GEMM (2 * STB)     // 73728 bytes

__global__ void __launch_bounds__(128, 2) gemm_mma(
    const __half* __restrict__ A,
    const __half* __restrict__ Bt,
    const float* __restrict__ bias,
    float* __restrict__ Cf,
    __half* __restrict__ Ch,
    int N, int fuse)
{
    extern __shared__ __half smbuf[];
    const uint32_t smem0 = (uint32_t)__cvta_generic_to_shared(smbuf);

    const int tid  = threadIdx.x;
    const int m0   = blockIdx.y * 128;
    const int n0   = blockIdx.x * 128;
    const int warp = tid >> 5;
    const int lane = tid & 31;
    const int wm   = (warp >> 1) * 64;
    const int wn   = (warp & 1) * 64;
    const int gm   = lane >> 2;
    const int kq   = (lane & 3) * 2;

    const uint32_t aOff = (uint32_t)(((wm + (lane & 7) + ((lane >> 3) & 1) * 8) * RS
                                      + (lane >> 4) * 8) * 2);
    const uint32_t bOff = (uint32_t)(TEL * 2 +
                                     ((wn + (lane & 7) + ((lane >> 4) & 1) * 8) * RS
                                      + ((lane >> 3) & 1) * 8) * 2);

    float acc[4][8][4];
    #pragma unroll
    for (int i = 0; i < 4; i++)
        #pragma unroll
        for (int j = 0; j < 8; j++)
            #pragma unroll
            for (int t = 0; t < 4; t++)
                acc[i][j][t] = 0.f;

    const int lr  = tid >> 3;
    const int ljh = (tid & 7) * 8;
    auto load_chunk = [&](int ci, int st) {
        const size_t kof = (size_t)(ci << 6);
        __half* As = smbuf + (size_t)st * SEL;
        __half* Bs = As + TEL;
        #pragma unroll
        for (int h = 0; h < 8; h++) {
            int r = lr + h * 16;
            cpa16(As + r * RS + ljh, A  + (size_t)(m0 + r) * KH + kof + ljh);
            cpa16(Bs + r * RS + ljh, Bt + (size_t)(n0 + r) * KH + kof + ljh);
        }
        asm volatile("cp.async.commit_group;");
    };

    load_chunk(0, 0);

    const int NCH = 16;
    for (int ci = 0; ci < NCH; ci++) {
        const int st = ci & 1;
        asm volatile("cp.async.wait_group 0;" ::: "memory");
        __syncthreads();
        if (ci + 1 < NCH) load_chunk(ci + 1, st ^ 1);

        const uint32_t aBase = smem0 + (uint32_t)st * STB + aOff;
        const uint32_t bBase = smem0 + (uint32_t)st * STB + bOff;

        #pragma unroll
        for (int kk = 0; kk < 4; kk++) {
            uint32_t af[4][4], bf[8][2];
            #pragma unroll
            for (int i = 0; i < 4; i++)
                asm volatile(
                    "ldmatrix.sync.aligned.m8n8.x4.shared.b16 {%0,%1,%2,%3}, [%4];"
                    : "=r"(af[i][0]), "=r"(af[i][1]), "=r"(af[i][2]), "=r"(af[i][3])
                    : "r"(aBase + (uint32_t)(i * 16 * RS * 2 + kk * 32)));
            #pragma unroll
            for (int j = 0; j < 4; j++)
                asm volatile(
                    "ldmatrix.sync.aligned.m8n8.x4.shared.b16 {%0,%1,%2,%3}, [%4];"
                    : "=r"(bf[2*j][0]), "=r"(bf[2*j][1]),
                      "=r"(bf[2*j+1][0]), "=r"(bf[2*j+1][1])
                    : "r"(bBase + (uint32_t)(j * 16 * RS * 2 + kk * 32)));
            #pragma unroll
            for (int i = 0; i < 4; i++)
                #pragma unroll
                for (int j = 0; j < 8; j++) HMMA(acc[i][j], af[i], bf[j]);
        }
    }

    if (fuse) {
        // seg 0: sigmoid(r), seg 1: exp(k), seg 2: v  -> fp16
        const int seg = n0 >> 10;
        #pragma unroll
        for (int j = 0; j < 8; j++) {
            const int col = n0 + wn + j * 8 + kq;
            const float b0 = bias[col], b1 = bias[col + 1];
            #pragma unroll
            for (int i = 0; i < 4; i++) {
                const int row = m0 + wm + i * 16 + gm;
                float f[4] = { acc[i][j][0] + b0, acc[i][j][1] + b1,
                               acc[i][j][2] + b0, acc[i][j][3] + b1 };
                #pragma unroll
                for (int t = 0; t < 4; t++) {
                    if (seg == 0)      f[t] = 1.f / (1.f + expf(-f[t]));
                    else if (seg == 1) f[t] = expf(f[t]);
                }
                __half2 h0 = __floats2half2_rn(f[0], f[1]);
                __half2 h1 = __floats2half2_rn(f[2], f[3]);
                *(__half2*)&Ch[(size_t)row * N + col]       = h0;
                *(__half2*)&Ch[(size_t)(row + 8) * N + col] = h1;
            }
        }
    } else {
        #pragma unroll
        for (int j = 0; j < 8; j++) {
            const int col = n0 + wn + j * 8 + kq;
            const float b0 = bias[col], b1 = bias[col + 1];
            #pragma unroll
            for (int i = 0; i < 4; i++) {
                const int row = m0 + wm + i * 16 + gm;
                float2 v0 = make_float2(acc[i][j][0] + b0, acc[i][j][1] + b1);
                float2 v1 = make_float2(acc[i][j][2] + b0, acc[i][j][3] + b1);
                *(float2*)&Cf[(size_t)row * N + col]       = v0;
                *(float2*)&Cf[(size_t)(row + 8) * N + col] = v1;
            }
        }
    }
}

// ---------------------------------------------------------------------------
// fp32 -> fp16 cast, [R,1024] contiguous
// ---------------------------------------------------------------------------
__global__ void __launch_bounds__(256) tohalf_rows(const float* __restrict__ X,
                                                   __half* __restrict__ Y, int total4)
{
    int idx = blockIdx.x * 256 + threadIdx.x;
    if (idx >= total4) return;
    float4 v = ((const float4*)X)[idx];
    ((__half2*)Y)[idx * 2]     = __floats2half2_rn(v.x, v.y);
    ((__half2*)Y)[idx * 2 + 1] = __floats2half2_rn(v.z, v.w);
}

// ---------------------------------------------------------------------------
// W[K,Ncols] fp32 -> Bt[n,1024] fp16 (transpose + cast), tiled 32x32
// ---------------------------------------------------------------------------
__global__ void halfcast_T(const float* __restrict__ W, __half* __restrict__ Bt,
                           int Ncols)
{
    __shared__ float t[32][33];
    int n = blockIdx.x * 32 + threadIdx.x;
    int k0 = blockIdx.y * 32;
    for (int i = threadIdx.y; i < 32; i += 8)
        t[i][threadIdx.x] = W[(size_t)(k0 + i) * Ncols + n];
    __syncthreads();
    int k = k0 + threadIdx.x;
    for (int i = threadIdx.y; i < 32; i += 8) {
        int nn = blockIdx.x * 32 + i;
        Bt[(size_t)nn * KH + k] = __float2half_rn(t[threadIdx.x][i]);
    }
}

// ---------------------------------------------------------------------------
// Chunked linear-recurrence scan. Inputs are pre-activated fp16:
// g_rkv16[:, 0:1024)=sigmoid(r), [1024:2048)=exp(k), [2048:3072)=v.
// Phase A: per-chunk local scan partials (read-only; kv recomputed).
// Phase B: serial prefix across chunks.
// Phase C: re-scan + x output (fp16).
// ---------------------------------------------------------------------------
__global__ void __launch_bounds__(256) scan_phaseA(const float* __restrict__ nu_log)
{
    const int c = blockIdx.x * blockDim.x + threadIdx.x;
    const int chunk = blockIdx.y;
    const int b = blockIdx.z;
    const float lam = expf(-expf(nu_log[c]));

    size_t base = ((size_t)b * LSEQ + (size_t)chunk * LC) * U3;
    float y1 = 0.f, y2 = 0.f;
    #pragma unroll 4
    for (int i = 0; i < LC; i++) {
        size_t off = base + (size_t)i * U3;
        float kk = __half2float(g_rkv16[off + UD + c]);
        float vv = __half2float(g_rkv16[off + 2 * UD + c]);
        y1 = fmaf(y1, lam, kk * vv);
        y2 = fmaf(y2, lam, kk);
    }
    size_t p = (size_t)(b * NCHUNK + chunk) * 2 * UD + c;
    g_part[p]      = y1;
    g_part[p + UD] = y2;
}

__global__ void __launch_bounds__(256) scan_phaseB(const float* __restrict__ nu_log)
{
    const int c = blockIdx.x * blockDim.x + threadIdx.x;
    const int b = blockIdx.y;
    const float lam = expf(-expf(nu_log[c]));
    const float lamLc = powf(lam, (float)LC);
    float Y1 = 0.f, Y2 = 0.f;
    for (int j = 0; j < NCHUNK; j++) {
        size_t p = (size_t)(b * NCHUNK + j) * 2 * UD + c;
        float S1 = g_part[p], S2 = g_part[p + UD];
        g_part[p]      = Y1;
        g_part[p + UD] = Y2;
        Y1 = fmaf(Y1, lamLc, S1);
        Y2 = fmaf(Y2, lamLc, S2);
    }
}

__global__ void __launch_bounds__(256) scan_phaseC(const float* __restrict__ nu_log,
                                                   const float* __restrict__ gamma_log)
{
    const int c = blockIdx.x * blockDim.x + threadIdx.x;
    const int chunk = blockIdx.y;
    const int b = blockIdx.z;
    const float lam = expf(-expf(nu_log[c]));
    const float gamma = expf(nu_log[c] + gamma_log[c]) - 1.f;

    size_t p = (size_t)(b * NCHUNK + chunk) * 2 * UD + c;
    float y1 = g_part[p];
    float y2 = g_part[p + UD];

    size_t base  = ((size_t)b * LSEQ + (size_t)chunk * LC) * U3;
    size_t xbase = ((size_t)b * LSEQ + (size_t)chunk * LC) * UD;
    #pragma unroll 4
    for (int i = 0; i < LC; i++) {
        size_t off = base + (size_t)i * U3;
        float sr = __half2float(g_rkv16[off + c]);             // sigmoid(r)
        float kk = __half2float(g_rkv16[off + UD + c]);        // exp(k)
        float vv = __half2float(g_rkv16[off + 2 * UD + c]);    // v
        float kv = kk * vv;
        y1 = fmaf(y1, lam, kv);
        y2 = fmaf(y2, lam, kk);
        float x = (y1 + gamma * kv) / (y2 + gamma * kk + 1e-6f) * sr;
        g_X16[xbase + (size_t)i * UD + c] = __float2half_rn(x);
    }
}

// ---------------------------------------------------------------------------
// Launch
// ---------------------------------------------------------------------------
extern "C" void kernel_launch(void* const* d_in, const int* in_sizes, int n_in,
                              void* d_out, int out_size)
{
    const float* inputs    = (const float*)d_in[0];
    const float* W_rkv     = (const float*)d_in[1];
    const float* b_rkv     = (const float*)d_in[2];
    const float* W_o       = (const float*)d_in[3];
    const float* b_o       = (const float*)d_in[4];
    const float* nu_log    = (const float*)d_in[5];
    const float* gamma_log = (const float*)d_in[6];
    float* out = (float*)d_out;

    __half *p_rkv16 = nullptr, *p_A16 = nullptr, *p_X16 = nullptr,
           *p_B1 = nullptr, *p_B2 = nullptr;
    cudaGetSymbolAddress((void**)&p_rkv16, g_rkv16);
    cudaGetSymbolAddress((void**)&p_A16, g_A16);
    cudaGetSymbolAddress((void**)&p_X16, g_X16);
    cudaGetSymbolAddress((void**)&p_B1, g_B1);
    cudaGetSymbolAddress((void**)&p_B2, g_B2);

    static bool attr_set = false;
    if (!attr_set) {
        cudaFuncSetAttribute(gemm_mma, cudaFuncAttributeMaxDynamicSharedMemorySize, SMEM_GEMM);
        attr_set = true;
    }

    // Operand conversion: A -> fp16; W -> fp16, transposed
    tohalf_rows<<<(MROWS * 256 + 255) / 256, 256>>>(inputs, p_A16, MROWS * 256);
    halfcast_T<<<dim3(U3 / 32, HD / 32), dim3(32, 8)>>>(W_rkv, p_B1, U3);
    halfcast_T<<<dim3(HD / 32, UD / 32), dim3(32, 8)>>>(W_o, p_B2, HD);

    // GEMM1 (fused epilogue): g_rkv16 = act(inputs @ W_rkv + b_rkv)
    gemm_mma<<<dim3(U3 / 128, MROWS / 128), 128, SMEM_GEMM>>>(
        p_A16, p_B1, b_rkv, nullptr, p_rkv16, U3, 1);

    // Scan (phase C writes x directly as fp16)
    scan_phaseA<<<dim3(UD / 256, NCHUNK, BB), 256>>>(nu_log);
    scan_phaseB<<<dim3(UD / 256, BB), 256>>>(nu_log);
    scan_phaseC<<<dim3(UD / 256, NCHUNK, BB), 256>>>(nu_log, gamma_log);

    // GEMM2: out = x @ W_o + b_o   [16384, 1024] fp32
    gemm_mma<<<dim3(HD / 128, MROWS / 128), 128, SMEM_GEMM>>>(
        p_X16, p_B2, b_o, out, nullptr, HD, 0);
}

// round 15
// speedup vs baseline: 1.0285x; 1.0285x over previous
#include <cuda_runtime.h>
#include <cuda_fp16.h>
#include <math.h>
#include <stdint.h>

// Problem constants
#define BB   4
#define LSEQ 4096
#define HD   1024
#define UD   1024
#define U3   3072
#define NCHUNK 64
#define LC     64
#define KH   1024           // operand K width (fp16)
#define MROWS (BB*LSEQ)     // 16384

// Scratch (allocation-free: __device__ globals)
__device__ __half g_rkv16[(size_t)BB * LSEQ * U3];     // 96 MB: sigmoid(r), exp(k), v
__device__ float g_part[(size_t)BB * NCHUNK * 2 * UD]; // 2 MB
__device__ __half g_A16[(size_t)MROWS * KH];           // 32 MB fp16(inputs)
__device__ __half g_X16[(size_t)MROWS * KH];           // 32 MB fp16(x), written by scan
__device__ __half g_B1[(size_t)U3 * KH];               //  6 MB T(W_rkv) fp16
__device__ __half g_B2[(size_t)HD * KH];               //  2 MB T(W_o) fp16

__device__ __forceinline__ void cpa16(void* s, const void* g) {
    uint32_t sa = (uint32_t)__cvta_generic_to_shared(s);
    asm volatile("cp.async.cg.shared.global [%0], [%1], 16;" :: "r"(sa), "l"(g));
}

#define HMMA(d, a, b) \
    asm volatile( \
        "mma.sync.aligned.m16n8k16.row.col.f32.f16.f16.f32 " \
        "{%0,%1,%2,%3},{%4,%5,%6,%7},{%8,%9},{%0,%1,%2,%3};" \
        : "+f"(d[0]), "+f"(d[1]), "+f"(d[2]), "+f"(d[3]) \
        : "r"(a[0]), "r"(a[1]), "r"(a[2]), "r"(a[3]), "r"(b[0]), "r"(b[1]))

// ---------------------------------------------------------------------------
// fp16 warp-MMA GEMM (mma.sync m16n8k16, fp32 accum), single product.
// 16 k64-chunks. CTA tile 128x128, 4 warps (2x2), warp tile 64x64, 128 thr,
// 2 CTAs/SM. 2-stage cp.async pipeline, ldmatrix.x4.
// SMEM rows: 128B data + 16B pad = 144B (conflict-free).
// FUSE=1: per-segment fast nonlinearity (sigmoid/exp/id) -> fp16 out
// FUSE=0: bias -> fp32 out
// ---------------------------------------------------------------------------
#define RS    72                // row stride (fp16 elems) = 144 B
#define TEL   (128 * RS)
#define SEL   (2 * TEL)
#define STB   (SEL * 2)         // 36864 bytes
#define SMEM_GEMM (2 * STB)     // 73728 bytes

template <int FUSE>
__global__ void __launch_bounds__(128, 2) gemm_mma(
    const __half* __restrict__ A,
    const __half* __restrict__ Bt,
    const float* __restrict__ bias,
    float* __restrict__ Cf,
    __half* __restrict__ Ch,
    int N)
{
    extern __shared__ __half smbuf[];
    const uint32_t smem0 = (uint32_t)__cvta_generic_to_shared(smbuf);

    const int tid  = threadIdx.x;
    const int m0   = blockIdx.y * 128;
    const int n0   = blockIdx.x * 128;
    const int warp = tid >> 5;
    const int lane = tid & 31;
    const int wm   = (warp >> 1) * 64;
    const int wn   = (warp & 1) * 64;
    const int gm   = lane >> 2;
    const int kq   = (lane & 3) * 2;

    const uint32_t aOff = (uint32_t)(((wm + (lane & 7) + ((lane >> 3) & 1) * 8) * RS
                                      + (lane >> 4) * 8) * 2);
    const uint32_t bOff = (uint32_t)(TEL * 2 +
                                     ((wn + (lane & 7) + ((lane >> 4) & 1) * 8) * RS
                                      + ((lane >> 3) & 1) * 8) * 2);

    float acc[4][8][4];
    #pragma unroll
    for (int i = 0; i < 4; i++)
        #pragma unroll
        for (int j = 0; j < 8; j++)
            #pragma unroll
            for (int t = 0; t < 4; t++)
                acc[i][j][t] = 0.f;

    const int lr  = tid >> 3;
    const int ljh = (tid & 7) * 8;
    auto load_chunk = [&](int ci, int st) {
        const size_t kof = (size_t)(ci << 6);
        __half* As = smbuf + (size_t)st * SEL;
        __half* Bs = As + TEL;
        #pragma unroll
        for (int h = 0; h < 8; h++) {
            int r = lr + h * 16;
            cpa16(As + r * RS + ljh, A  + (size_t)(m0 + r) * KH + kof + ljh);
            cpa16(Bs + r * RS + ljh, Bt + (size_t)(n0 + r) * KH + kof + ljh);
        }
        asm volatile("cp.async.commit_group;");
    };

    load_chunk(0, 0);

    const int NCH = 16;
    for (int ci = 0; ci < NCH; ci++) {
        const int st = ci & 1;
        asm volatile("cp.async.wait_group 0;" ::: "memory");
        __syncthreads();
        if (ci + 1 < NCH) load_chunk(ci + 1, st ^ 1);

        const uint32_t aBase = smem0 + (uint32_t)st * STB + aOff;
        const uint32_t bBase = smem0 + (uint32_t)st * STB + bOff;

        #pragma unroll
        for (int kk = 0; kk < 4; kk++) {
            uint32_t af[4][4], bf[8][2];
            #pragma unroll
            for (int i = 0; i < 4; i++)
                asm volatile(
                    "ldmatrix.sync.aligned.m8n8.x4.shared.b16 {%0,%1,%2,%3}, [%4];"
                    : "=r"(af[i][0]), "=r"(af[i][1]), "=r"(af[i][2]), "=r"(af[i][3])
                    : "r"(aBase + (uint32_t)(i * 16 * RS * 2 + kk * 32)));
            #pragma unroll
            for (int j = 0; j < 4; j++)
                asm volatile(
                    "ldmatrix.sync.aligned.m8n8.x4.shared.b16 {%0,%1,%2,%3}, [%4];"
                    : "=r"(bf[2*j][0]), "=r"(bf[2*j][1]),
                      "=r"(bf[2*j+1][0]), "=r"(bf[2*j+1][1])
                    : "r"(bBase + (uint32_t)(j * 16 * RS * 2 + kk * 32)));
            #pragma unroll
            for (int i = 0; i < 4; i++)
                #pragma unroll
                for (int j = 0; j < 8; j++) HMMA(acc[i][j], af[i], bf[j]);
        }
    }

    if (FUSE) {
        // seg 0: sigmoid(r), seg 1: exp(k), seg 2: v  -> fp16 (fast MUFU math)
        const int seg = n0 >> 10;
        #pragma unroll
        for (int j = 0; j < 8; j++) {
            const int col = n0 + wn + j * 8 + kq;
            const float b0 = bias[col], b1 = bias[col + 1];
            #pragma unroll
            for (int i = 0; i < 4; i++) {
                const int row = m0 + wm + i * 16 + gm;
                float f[4] = { acc[i][j][0] + b0, acc[i][j][1] + b1,
                               acc[i][j][2] + b0, acc[i][j][3] + b1 };
                #pragma unroll
                for (int t = 0; t < 4; t++) {
                    if (seg == 0)      f[t] = __frcp_rn(1.f + __expf(-f[t]));
                    else if (seg == 1) f[t] = __expf(f[t]);
                }
                __half2 h0 = __floats2half2_rn(f[0], f[1]);
                __half2 h1 = __floats2half2_rn(f[2], f[3]);
                *(__half2*)&Ch[(size_t)row * N + col]       = h0;
                *(__half2*)&Ch[(size_t)(row + 8) * N + col] = h1;
            }
        }
    } else {
        #pragma unroll
        for (int j = 0; j < 8; j++) {
            const int col = n0 + wn + j * 8 + kq;
            const float b0 = bias[col], b1 = bias[col + 1];
            #pragma unroll
            for (int i = 0; i < 4; i++) {
                const int row = m0 + wm + i * 16 + gm;
                float2 v0 = make_float2(acc[i][j][0] + b0, acc[i][j][1] + b1);
                float2 v1 = make_float2(acc[i][j][2] + b0, acc[i][j][3] + b1);
                *(float2*)&Cf[(size_t)row * N + col]       = v0;
                *(float2*)&Cf[(size_t)(row + 8) * N + col] = v1;
            }
        }
    }
}

// ---------------------------------------------------------------------------
// fp32 -> fp16 cast, [R,1024] contiguous
// ---------------------------------------------------------------------------
__global__ void __launch_bounds__(256) tohalf_rows(const float* __restrict__ X,
                                                   __half* __restrict__ Y, int total4)
{
    int idx = blockIdx.x * 256 + threadIdx.x;
    if (idx >= total4) return;
    float4 v = ((const float4*)X)[idx];
    ((__half2*)Y)[idx * 2]     = __floats2half2_rn(v.x, v.y);
    ((__half2*)Y)[idx * 2 + 1] = __floats2half2_rn(v.z, v.w);
}

// ---------------------------------------------------------------------------
// W[K,Ncols] fp32 -> Bt[n,1024] fp16 (transpose + cast), tiled 32x32
// ---------------------------------------------------------------------------
__global__ void halfcast_T(const float* __restrict__ W, __half* __restrict__ Bt,
                           int Ncols)
{
    __shared__ float t[32][33];
    int n = blockIdx.x * 32 + threadIdx.x;
    int k0 = blockIdx.y * 32;
    for (int i = threadIdx.y; i < 32; i += 8)
        t[i][threadIdx.x] = W[(size_t)(k0 + i) * Ncols + n];
    __syncthreads();
    int k = k0 + threadIdx.x;
    for (int i = threadIdx.y; i < 32; i += 8) {
        int nn = blockIdx.x * 32 + i;
        Bt[(size_t)nn * KH + k] = __float2half_rn(t[threadIdx.x][i]);
    }
}

// ---------------------------------------------------------------------------
// Chunked linear-recurrence scan. Inputs are pre-activated fp16:
// g_rkv16[:, 0:1024)=sigmoid(r), [1024:2048)=exp(k), [2048:3072)=v.
// ---------------------------------------------------------------------------
__global__ void __launch_bounds__(256) scan_phaseA(const float* __restrict__ nu_log)
{
    const int c = blockIdx.x * blockDim.x + threadIdx.x;
    const int chunk = blockIdx.y;
    const int b = blockIdx.z;
    const float lam = expf(-expf(nu_log[c]));

    size_t base = ((size_t)b * LSEQ + (size_t)chunk * LC) * U3;
    float y1 = 0.f, y2 = 0.f;
    #pragma unroll 4
    for (int i = 0; i < LC; i++) {
        size_t off = base + (size_t)i * U3;
        float kk = __half2float(g_rkv16[off + UD + c]);
        float vv = __half2float(g_rkv16[off + 2 * UD + c]);
        y1 = fmaf(y1, lam, kk * vv);
        y2 = fmaf(y2, lam, kk);
    }
    size_t p = (size_t)(b * NCHUNK + chunk) * 2 * UD + c;
    g_part[p]      = y1;
    g_part[p + UD] = y2;
}

__global__ void __launch_bounds__(256) scan_phaseB(const float* __restrict__ nu_log)
{
    const int c = blockIdx.x * blockDim.x + threadIdx.x;
    const int b = blockIdx.y;
    const float lam = expf(-expf(nu_log[c]));
    const float lamLc = powf(lam, (float)LC);
    float Y1 = 0.f, Y2 = 0.f;
    for (int j = 0; j < NCHUNK; j++) {
        size_t p = (size_t)(b * NCHUNK + j) * 2 * UD + c;
        float S1 = g_part[p], S2 = g_part[p + UD];
        g_part[p]      = Y1;
        g_part[p + UD] = Y2;
        Y1 = fmaf(Y1, lamLc, S1);
        Y2 = fmaf(Y2, lamLc, S2);
    }
}

__global__ void __launch_bounds__(256) scan_phaseC(const float* __restrict__ nu_log,
                                                   const float* __restrict__ gamma_log)
{
    const int c = blockIdx.x * blockDim.x + threadIdx.x;
    const int chunk = blockIdx.y;
    const int b = blockIdx.z;
    const float lam = expf(-expf(nu_log[c]));
    const float gamma = expf(nu_log[c] + gamma_log[c]) - 1.f;

    size_t p = (size_t)(b * NCHUNK + chunk) * 2 * UD + c;
    float y1 = g_part[p];
    float y2 = g_part[p + UD];

    size_t base  = ((size_t)b * LSEQ + (size_t)chunk * LC) * U3;
    size_t xbase = ((size_t)b * LSEQ + (size_t)chunk * LC) * UD;
    #pragma unroll 4
    for (int i = 0; i < LC; i++) {
        size_t off = base + (size_t)i * U3;
        float sr = __half2float(g_rkv16[off + c]);             // sigmoid(r)
        float kk = __half2float(g_rkv16[off + UD + c]);        // exp(k)
        float vv = __half2float(g_rkv16[off + 2 * UD + c]);    // v
        float kv = kk * vv;
        y1 = fmaf(y1, lam, kv);
        y2 = fmaf(y2, lam, kk);
        float x = (y1 + gamma * kv) / (y2 + gamma * kk + 1e-6f) * sr;
        g_X16[xbase + (size_t)i * UD + c] = __float2half_rn(x);
    }
}

// ---------------------------------------------------------------------------
// Launch
// ---------------------------------------------------------------------------
extern "C" void kernel_launch(void* const* d_in, const int* in_sizes, int n_in,
                              void* d_out, int out_size)
{
    const float* inputs    = (const float*)d_in[0];
    const float* W_rkv     = (const float*)d_in[1];
    const float* b_rkv     = (const float*)d_in[2];
    const float* W_o       = (const float*)d_in[3];
    const float* b_o       = (const float*)d_in[4];
    const float* nu_log    = (const float*)d_in[5];
    const float* gamma_log = (const float*)d_in[6];
    float* out = (float*)d_out;

    __half *p_rkv16 = nullptr, *p_A16 = nullptr, *p_X16 = nullptr,
           *p_B1 = nullptr, *p_B2 = nullptr;
    cudaGetSymbolAddress((void**)&p_rkv16, g_rkv16);
    cudaGetSymbolAddress((void**)&p_A16, g_A16);
    cudaGetSymbolAddress((void**)&p_X16, g_X16);
    cudaGetSymbolAddress((void**)&p_B1, g_B1);
    cudaGetSymbolAddress((void**)&p_B2, g_B2);

    static bool attr_set = false;
    if (!attr_set) {
        cudaFuncSetAttribute(gemm_mma<1>, cudaFuncAttributeMaxDynamicSharedMemorySize, SMEM_GEMM);
        cudaFuncSetAttribute(gemm_mma<0>, cudaFuncAttributeMaxDynamicSharedMemorySize, SMEM_GEMM);
        attr_set = true;
    }

    // Operand conversion: A -> fp16; W -> fp16, transposed
    tohalf_rows<<<(MROWS * 256 + 255) / 256, 256>>>(inputs, p_A16, MROWS * 256);
    halfcast_T<<<dim3(U3 / 32, HD / 32), dim3(32, 8)>>>(W_rkv, p_B1, U3);
    halfcast_T<<<dim3(HD / 32, UD / 32), dim3(32, 8)>>>(W_o, p_B2, HD);

    // GEMM1 (fused fast-activation epilogue): g_rkv16 = act(inputs @ W_rkv + b_rkv)
    gemm_mma<1><<<dim3(U3 / 128, MROWS / 128), 128, SMEM_GEMM>>>(
        p_A16, p_B1, b_rkv, nullptr, p_rkv16, U3);

    // Scan (phase C writes x directly as fp16)
    scan_phaseA<<<dim3(UD / 256, NCHUNK, BB), 256>>>(nu_log);
    scan_phaseB<<<dim3(UD / 256, BB), 256>>>(nu_log);
    scan_phaseC<<<dim3(UD / 256, NCHUNK, BB), 256>>>(nu_log, gamma_log);

    // GEMM2: out = x @ W_o + b_o   [16384, 1024] fp32
    gemm_mma<0><<<dim3(HD / 128, MROWS / 128), 128, SMEM_GEMM>>>(
        p_X16, p_B2, b_o, out, nullptr, HD);
}

// round 16
// speedup vs baseline: 1.0360x; 1.0073x over previous
#include <cuda_runtime.h>
#include <cuda_fp16.h>
#include <math.h>
#include <stdint.h>

// Problem constants
#define BB   4
#define LSEQ 4096
#define HD   1024
#define UD   1024
#define U3   3072
#define NCHUNK 64
#define LC     64
#define KH   1024           // operand K width (fp16)
#define MROWS (BB*LSEQ)     // 16384

// Scratch (allocation-free: __device__ globals)
__device__ __half g_rkv16[(size_t)BB * LSEQ * U3];     // 96 MB: sigmoid(r), exp(k), v
__device__ float g_part[(size_t)BB * NCHUNK * 2 * UD]; // 2 MB
__device__ __half g_A16[(size_t)MROWS * KH];           // 32 MB fp16(inputs)
__device__ __half g_X16[(size_t)MROWS * KH];           // 32 MB fp16(x), written by scan
__device__ __half g_B1[(size_t)U3 * KH];               //  6 MB T(W_rkv) fp16
__device__ __half g_B2[(size_t)HD * KH];               //  2 MB T(W_o) fp16

__device__ __forceinline__ void cpa16(void* s, const void* g) {
    uint32_t sa = (uint32_t)__cvta_generic_to_shared(s);
    asm volatile("cp.async.cg.shared.global [%0], [%1], 16;" :: "r"(sa), "l"(g));
}
__device__ __forceinline__ float ex2f(float x) {
    float y; asm("ex2.approx.f32 %0, %1;" : "=f"(y) : "f"(x)); return y;
}
__device__ __forceinline__ float rcpf(float x) {
    float y; asm("rcp.approx.f32 %0, %1;" : "=f"(y) : "f"(x)); return y;
}
#define LOG2E 1.4426950408889634f

#define HMMA(d, a, b) \
    asm volatile( \
        "mma.sync.aligned.m16n8k16.row.col.f32.f16.f16.f32 " \
        "{%0,%1,%2,%3},{%4,%5,%6,%7},{%8,%9},{%0,%1,%2,%3};" \
        : "+f"(d[0]), "+f"(d[1]), "+f"(d[2]), "+f"(d[3]) \
        : "r"(a[0]), "r"(a[1]), "r"(a[2]), "r"(a[3]), "r"(b[0]), "r"(b[1]))

// ---------------------------------------------------------------------------
// fp16 warp-MMA GEMM (mma.sync m16n8k16, fp32 accum), single product.
// 16 k64-chunks. CTA tile 128x128, 4 warps (2x2), warp tile 64x64, 128 thr,
// 2 CTAs/SM. 3-stage cp.async pipeline, ldmatrix.x4.
// SMEM rows: 128B data + 16B pad = 144B (conflict-free).
// FUSE=1: per-segment pure-MUFU nonlinearity (sigmoid/exp/id) -> fp16 out
// FUSE=0: bias -> fp32 out
// ---------------------------------------------------------------------------
#define RS    72                // row stride (fp16 elems) = 144 B
#define TEL   (128 * RS)
#define SEL   (2 * TEL)
#define STB   (SEL * 2)         // 36864 bytes per stage
#define SMEM_GEMM (3 * STB)     // 110592 bytes

template <int FUSE>
__global__ void __launch_bounds__(128, 2) gemm_mma(
    const __half* __restrict__ A,
    const __half* __restrict__ Bt,
    const float* __restrict__ bias,
    float* __restrict__ Cf,
    __half* __restrict__ Ch,
    int N)
{
    extern __shared__ __half smbuf[];
    const uint32_t smem0 = (uint32_t)__cvta_generic_to_shared(smbuf);

    const int tid  = threadIdx.x;
    const int m0   = blockIdx.y * 128;
    const int n0   = blockIdx.x * 128;
    const int warp = tid >> 5;
    const int lane = tid & 31;
    const int wm   = (warp >> 1) * 64;
    const int wn   = (warp & 1) * 64;
    const int gm   = lane >> 2;
    const int kq   = (lane & 3) * 2;

    const uint32_t aOff = (uint32_t)(((wm + (lane & 7) + ((lane >> 3) & 1) * 8) * RS
                                      + (lane >> 4) * 8) * 2);
    const uint32_t bOff = (uint32_t)(TEL * 2 +
                                     ((wn + (lane & 7) + ((lane >> 4) & 1) * 8) * RS
                                      + ((lane >> 3) & 1) * 8) * 2);

    float acc[4][8][4];
    #pragma unroll
    for (int i = 0; i < 4; i++)
        #pragma unroll
        for (int j = 0; j < 8; j++)
            #pragma unroll
            for (int t = 0; t < 4; t++)
                acc[i][j][t] = 0.f;

    const int lr  = tid >> 3;
    const int ljh = (tid & 7) * 8;
    auto load_chunk = [&](int ci, int st) {
        const size_t kof = (size_t)(ci << 6);
        __half* As = smbuf + (size_t)st * SEL;
        __half* Bs = As + TEL;
        #pragma unroll
        for (int h = 0; h < 8; h++) {
            int r = lr + h * 16;
            cpa16(As + r * RS + ljh, A  + (size_t)(m0 + r) * KH + kof + ljh);
            cpa16(Bs + r * RS + ljh, Bt + (size_t)(n0 + r) * KH + kof + ljh);
        }
        asm volatile("cp.async.commit_group;");
    };

    load_chunk(0, 0);
    load_chunk(1, 1);

    const int NCH = 16;
    for (int ci = 0; ci < NCH; ci++) {
        const int st = ci % 3;
        if (ci < NCH - 1) {
            asm volatile("cp.async.wait_group 1;" ::: "memory");
        } else {
            asm volatile("cp.async.wait_group 0;" ::: "memory");
        }
        __syncthreads();
        if (ci + 2 < NCH) load_chunk(ci + 2, (ci + 2) % 3);

        const uint32_t aBase = smem0 + (uint32_t)st * STB + aOff;
        const uint32_t bBase = smem0 + (uint32_t)st * STB + bOff;

        #pragma unroll
        for (int kk = 0; kk < 4; kk++) {
            uint32_t af[4][4], bf[8][2];
            #pragma unroll
            for (int i = 0; i < 4; i++)
                asm volatile(
                    "ldmatrix.sync.aligned.m8n8.x4.shared.b16 {%0,%1,%2,%3}, [%4];"
                    : "=r"(af[i][0]), "=r"(af[i][1]), "=r"(af[i][2]), "=r"(af[i][3])
                    : "r"(aBase + (uint32_t)(i * 16 * RS * 2 + kk * 32)));
            #pragma unroll
            for (int j = 0; j < 4; j++)
                asm volatile(
                    "ldmatrix.sync.aligned.m8n8.x4.shared.b16 {%0,%1,%2,%3}, [%4];"
                    : "=r"(bf[2*j][0]), "=r"(bf[2*j][1]),
                      "=r"(bf[2*j+1][0]), "=r"(bf[2*j+1][1])
                    : "r"(bBase + (uint32_t)(j * 16 * RS * 2 + kk * 32)));
            #pragma unroll
            for (int i = 0; i < 4; i++)
                #pragma unroll
                for (int j = 0; j < 8; j++) HMMA(acc[i][j], af[i], bf[j]);
        }
    }

    if (FUSE) {
        // seg 0: sigmoid(r), seg 1: exp(k), seg 2: v  -> fp16 (pure MUFU)
        const int seg = n0 >> 10;
        #pragma unroll
        for (int j = 0; j < 8; j++) {
            const int col = n0 + wn + j * 8 + kq;
            const float b0 = bias[col], b1 = bias[col + 1];
            #pragma unroll
            for (int i = 0; i < 4; i++) {
                const int row = m0 + wm + i * 16 + gm;
                float f[4] = { acc[i][j][0] + b0, acc[i][j][1] + b1,
                               acc[i][j][2] + b0, acc[i][j][3] + b1 };
                #pragma unroll
                for (int t = 0; t < 4; t++) {
                    if (seg == 0)      f[t] = rcpf(1.f + ex2f(-f[t] * LOG2E));
                    else if (seg == 1) f[t] = ex2f(f[t] * LOG2E);
                }
                __half2 h0 = __floats2half2_rn(f[0], f[1]);
                __half2 h1 = __floats2half2_rn(f[2], f[3]);
                *(__half2*)&Ch[(size_t)row * N + col]       = h0;
                *(__half2*)&Ch[(size_t)(row + 8) * N + col] = h1;
            }
        }
    } else {
        #pragma unroll
        for (int j = 0; j < 8; j++) {
            const int col = n0 + wn + j * 8 + kq;
            const float b0 = bias[col], b1 = bias[col + 1];
            #pragma unroll
            for (int i = 0; i < 4; i++) {
                const int row = m0 + wm + i * 16 + gm;
                float2 v0 = make_float2(acc[i][j][0] + b0, acc[i][j][1] + b1);
                float2 v1 = make_float2(acc[i][j][2] + b0, acc[i][j][3] + b1);
                *(float2*)&Cf[(size_t)row * N + col]       = v0;
                *(float2*)&Cf[(size_t)(row + 8) * N + col] = v1;
            }
        }
    }
}

// ---------------------------------------------------------------------------
// fp32 -> fp16 cast, [R,1024] contiguous
// ---------------------------------------------------------------------------
__global__ void __launch_bounds__(256) tohalf_rows(const float* __restrict__ X,
                                                   __half* __restrict__ Y, int total4)
{
    int idx = blockIdx.x * 256 + threadIdx.x;
    if (idx >= total4) return;
    float4 v = ((const float4*)X)[idx];
    ((__half2*)Y)[idx * 2]     = __floats2half2_rn(v.x, v.y);
    ((__half2*)Y)[idx * 2 + 1] = __floats2half2_rn(v.z, v.w);
}

// ---------------------------------------------------------------------------
// W[K,Ncols] fp32 -> Bt[n,1024] fp16 (transpose + cast), tiled 32x32
// ---------------------------------------------------------------------------
__global__ void halfcast_T(const float* __restrict__ W, __half* __restrict__ Bt,
                           int Ncols)
{
    __shared__ float t[32][33];
    int n = blockIdx.x * 32 + threadIdx.x;
    int k0 = blockIdx.y * 32;
    for (int i = threadIdx.y; i < 32; i += 8)
        t[i][threadIdx.x] = W[(size_t)(k0 + i) * Ncols + n];
    __syncthreads();
    int k = k0 + threadIdx.x;
    for (int i = threadIdx.y; i < 32; i += 8) {
        int nn = blockIdx.x * 32 + i;
        Bt[(size_t)nn * KH + k] = __float2half_rn(t[threadIdx.x][i]);
    }
}

// ---------------------------------------------------------------------------
// Chunked linear-recurrence scan. Inputs are pre-activated fp16:
// g_rkv16[:, 0:1024)=sigmoid(r), [1024:2048)=exp(k), [2048:3072)=v.
// ---------------------------------------------------------------------------
__global__ void __launch_bounds__(256) scan_phaseA(const float* __restrict__ nu_log)
{
    const int c = blockIdx.x * blockDim.x + threadIdx.x;
    const int chunk = blockIdx.y;
    const int b = blockIdx.z;
    const float lam = expf(-expf(nu_log[c]));

    size_t base = ((size_t)b * LSEQ + (size_t)chunk * LC) * U3;
    float y1 = 0.f, y2 = 0.f;
    #pragma unroll 4
    for (int i = 0; i < LC; i++) {
        size_t off = base + (size_t)i * U3;
        float kk = __half2float(g_rkv16[off + UD + c]);
        float vv = __half2float(g_rkv16[off + 2 * UD + c]);
        y1 = fmaf(y1, lam, kk * vv);
        y2 = fmaf(y2, lam, kk);
    }
    size_t p = (size_t)(b * NCHUNK + chunk) * 2 * UD + c;
    g_part[p]      = y1;
    g_part[p + UD] = y2;
}

__global__ void __launch_bounds__(256) scan_phaseB(const float* __restrict__ nu_log)
{
    const int c = blockIdx.x * blockDim.x + threadIdx.x;
    const int b = blockIdx.y;
    const float lam = expf(-expf(nu_log[c]));
    const float lamLc = powf(lam, (float)LC);
    float Y1 = 0.f, Y2 = 0.f;
    for (int j = 0; j < NCHUNK; j++) {
        size_t p = (size_t)(b * NCHUNK + j) * 2 * UD + c;
        float S1 = g_part[p], S2 = g_part[p + UD];
        g_part[p]      = Y1;
        g_part[p + UD] = Y2;
        Y1 = fmaf(Y1, lamLc, S1);
        Y2 = fmaf(Y2, lamLc, S2);
    }
}

__global__ void __launch_bounds__(256) scan_phaseC(const float* __restrict__ nu_log,
                                                   const float* __restrict__ gamma_log)
{
    const int c = blockIdx.x * blockDim.x + threadIdx.x;
    const int chunk = blockIdx.y;
    const int b = blockIdx.z;
    const float lam = expf(-expf(nu_log[c]));
    const float gamma = expf(nu_log[c] + gamma_log[c]) - 1.f;

    size_t p = (size_t)(b * NCHUNK + chunk) * 2 * UD + c;
    float y1 = g_part[p];
    float y2 = g_part[p + UD];

    size_t base  = ((size_t)b * LSEQ + (size_t)chunk * LC) * U3;
    size_t xbase = ((size_t)b * LSEQ + (size_t)chunk * LC) * UD;
    #pragma unroll 4
    for (int i = 0; i < LC; i++) {
        size_t off = base + (size_t)i * U3;
        float sr = __half2float(g_rkv16[off + c]);             // sigmoid(r)
        float kk = __half2float(g_rkv16[off + UD + c]);        // exp(k)
        float vv = __half2float(g_rkv16[off + 2 * UD + c]);    // v
        float kv = kk * vv;
        y1 = fmaf(y1, lam, kv);
        y2 = fmaf(y2, lam, kk);
        float x = (y1 + gamma * kv) / (y2 + gamma * kk + 1e-6f) * sr;
        g_X16[xbase + (size_t)i * UD + c] = __float2half_rn(x);
    }
}

// ---------------------------------------------------------------------------
// Launch
// ---------------------------------------------------------------------------
extern "C" void kernel_launch(void* const* d_in, const int* in_sizes, int n_in,
                              void* d_out, int out_size)
{
    const float* inputs    = (const float*)d_in[0];
    const float* W_rkv     = (const float*)d_in[1];
    const float* b_rkv     = (const float*)d_in[2];
    const float* W_o       = (const float*)d_in[3];
    const float* b_o       = (const float*)d_in[4];
    const float* nu_log    = (const float*)d_in[5];
    const float* gamma_log = (const float*)d_in[6];
    float* out = (float*)d_out;

    __half *p_rkv16 = nullptr, *p_A16 = nullptr, *p_X16 = nullptr,
           *p_B1 = nullptr, *p_B2 = nullptr;
    cudaGetSymbolAddress((void**)&p_rkv16, g_rkv16);
    cudaGetSymbolAddress((void**)&p_A16, g_A16);
    cudaGetSymbolAddress((void**)&p_X16, g_X16);
    cudaGetSymbolAddress((void**)&p_B1, g_B1);
    cudaGetSymbolAddress((void**)&p_B2, g_B2);

    static bool attr_set = false;
    if (!attr_set) {
        cudaFuncSetAttribute(gemm_mma<1>, cudaFuncAttributeMaxDynamicSharedMemorySize, SMEM_GEMM);
        cudaFuncSetAttribute(gemm_mma<0>, cudaFuncAttributeMaxDynamicSharedMemorySize, SMEM_GEMM);
        attr_set = true;
    }

    // Operand conversion: A -> fp16; W -> fp16, transposed
    tohalf_rows<<<(MROWS * 256 + 255) / 256, 256>>>(inputs, p_A16, MROWS * 256);
    halfcast_T<<<dim3(U3 / 32, HD / 32), dim3(32, 8)>>>(W_rkv, p_B1, U3);
    halfcast_T<<<dim3(HD / 32, UD / 32), dim3(32, 8)>>>(W_o, p_B2, HD);

    // GEMM1 (fused MUFU-activation epilogue): g_rkv16 = act(inputs @ W_rkv + b_rkv)
    gemm_mma<1><<<dim3(U3 / 128, MROWS / 128), 128, SMEM_GEMM>>>(
        p_A16, p_B1, b_rkv, nullptr, p_rkv16, U3);

    // Scan (phase C writes x directly as fp16)
    scan_phaseA<<<dim3(UD / 256, NCHUNK, BB), 256>>>(nu_log);
    scan_phaseB<<<dim3(UD / 256, BB), 256>>>(nu_log);
    scan_phaseC<<<dim3(UD / 256, NCHUNK, BB), 256>>>(nu_log, gamma_log);

    // GEMM2: out = x @ W_o + b_o   [16384, 1024] fp32
    gemm_mma<0><<<dim3(HD / 128, MROWS / 128), 128, SMEM_GEMM>>>(
        p_X16, p_B2, b_o, out, nullptr, HD);
}